// round 3
// baseline (speedup 1.0000x reference)
#include <cuda_runtime.h>
#include <cuda_bf16.h>

#define NQ 8
#define NL 4
#define BATCHN 4096
#define FULLMASK 0xffffffffu

// One warp simulates one sample. Amplitude index = lane*8 + j (j = 0..7).
// Qubit q lives on index bit (7-q): bits 0..2 -> in-register (j), bits 3..7 -> lane bits.
__global__ __launch_bounds__(256) void vqc_kernel(
    const float* __restrict__ x,      // (BATCH, 8)
    const float* __restrict__ w,      // (4, 8, 2) flattened
    float* __restrict__ out)          // (BATCH,)
{
    __shared__ float wc[NL * NQ * 2];
    __shared__ float ws[NL * NQ * 2];
    const int tid = threadIdx.x;
    if (tid < NL * NQ * 2) {
        float a = 0.5f * w[tid];
        float s, c;
        sincosf(a, &s, &c);
        wc[tid] = c; ws[tid] = s;
    }
    __syncthreads();

    const int lane = tid & 31;
    const int sample = (blockIdx.x * blockDim.x + tid) >> 5;
    if (sample >= BATCHN) return;

    float re[8], im[8];
#pragma unroll
    for (int j = 0; j < 8; j++) { re[j] = 0.0f; im[j] = 0.0f; }
    if (lane == 0) re[0] = 1.0f;  // |00000000>

    // ---------------- Angle encoding: RY(x[q]) on qubit q ----------------
#pragma unroll
    for (int q = 0; q < NQ; q++) {
        float a = 0.5f * __ldg(&x[sample * NQ + q]);
        float s, c;
        __sincosf(a, &s, &c);
        const int bit = 7 - q;
        if (bit < 3) {
            const int step = 1 << bit;
#pragma unroll
            for (int j = 0; j < 8; j++) {
                if (!(j & step)) {
                    const int k = j | step;
                    float r0 = re[j], i0 = im[j], r1 = re[k], i1 = im[k];
                    re[j] = fmaf(-s, r1, c * r0); im[j] = fmaf(-s, i1, c * i0);
                    re[k] = fmaf( s, r0, c * r1); im[k] = fmaf( s, i0, c * i1);
                }
            }
        } else {
            const int lb = 1 << (bit - 3);
            const float ss = (lane & lb) ? s : -s;
#pragma unroll
            for (int j = 0; j < 8; j++) {
                float pr = __shfl_xor_sync(FULLMASK, re[j], lb);
                float pi = __shfl_xor_sync(FULLMASK, im[j], lb);
                re[j] = fmaf(ss, pr, c * re[j]);
                im[j] = fmaf(ss, pi, c * im[j]);
            }
        }
    }

    // ---------------- Variational layers ----------------
#pragma unroll 1
    for (int l = 0; l < NL; l++) {
        // CNOT ring: control i -> target (i+1) % 8
#pragma unroll
        for (int i = 0; i < NQ; i++) {
            const int bc = 7 - i;               // control bit
            const int bt = 7 - ((i + 1) & 7);   // target bit
            if (bt < 3) {
                const int tstep = 1 << bt;
                if (bc >= 3) {
                    // control = lane bit, target = register bit: swap regs when control set
                    const int clb = 1 << (bc - 3);
                    if (lane & clb) {
#pragma unroll
                        for (int j = 0; j < 8; j++) {
                            if (!(j & tstep)) {
                                const int k = j | tstep;
                                float tr = re[j]; re[j] = re[k]; re[k] = tr;
                                float ti = im[j]; im[j] = im[k]; im[k] = ti;
                            }
                        }
                    }
                } else {
                    // both control and target in registers
                    const int cstep = 1 << bc;
#pragma unroll
                    for (int j = 0; j < 8; j++) {
                        if (!(j & tstep) && (j & cstep)) {
                            const int k = j | tstep;
                            float tr = re[j]; re[j] = re[k]; re[k] = tr;
                            float ti = im[j]; im[j] = im[k]; im[k] = ti;
                        }
                    }
                }
            } else {
                // target = lane bit: exchange with partner lane, select if control set
                const int lb = 1 << (bt - 3);
#pragma unroll
                for (int j = 0; j < 8; j++) {
                    float pr = __shfl_xor_sync(FULLMASK, re[j], lb);
                    float pi = __shfl_xor_sync(FULLMASK, im[j], lb);
                    bool cb;
                    if (bc < 3) cb = ((j >> bc) & 1) != 0;          // compile-time per j
                    else        cb = ((lane >> (bc - 3)) & 1) != 0; // uniform over j
                    if (cb) { re[j] = pr; im[j] = pi; }
                }
            }
        }

        // RY(w[l,i,0]) then RZ(w[l,i,1]) on each qubit
#pragma unroll
        for (int i = 0; i < NQ; i++) {
            const int base = (l * NQ + i) * 2;
            const int bit = 7 - i;

            // ---- RY ----
            {
                const float c = wc[base], s = ws[base];
                if (bit < 3) {
                    const int step = 1 << bit;
#pragma unroll
                    for (int j = 0; j < 8; j++) {
                        if (!(j & step)) {
                            const int k = j | step;
                            float r0 = re[j], i0 = im[j], r1 = re[k], i1 = im[k];
                            re[j] = fmaf(-s, r1, c * r0); im[j] = fmaf(-s, i1, c * i0);
                            re[k] = fmaf( s, r0, c * r1); im[k] = fmaf( s, i0, c * i1);
                        }
                    }
                } else {
                    const int lb = 1 << (bit - 3);
                    const float ss = (lane & lb) ? s : -s;
#pragma unroll
                    for (int j = 0; j < 8; j++) {
                        float pr = __shfl_xor_sync(FULLMASK, re[j], lb);
                        float pi = __shfl_xor_sync(FULLMASK, im[j], lb);
                        re[j] = fmaf(ss, pr, c * re[j]);
                        im[j] = fmaf(ss, pi, c * im[j]);
                    }
                }
            }

            // ---- RZ (diagonal, no communication) ----
            // amplitude *= exp(i * sigma * theta/2), sigma = +1 if bit set else -1
            {
                const float c = wc[base + 1], s = ws[base + 1];
                if (bit < 3) {
#pragma unroll
                    for (int j = 0; j < 8; j++) {
                        const float sg = ((j >> bit) & 1) ? s : -s;
                        float r = re[j], q = im[j];
                        re[j] = fmaf(-sg, q, c * r);
                        im[j] = fmaf( sg, r, c * q);
                    }
                } else {
                    const float sg = (lane & (1 << (bit - 3))) ? s : -s;
#pragma unroll
                    for (int j = 0; j < 8; j++) {
                        float r = re[j], q = im[j];
                        re[j] = fmaf(-sg, q, c * r);
                        im[j] = fmaf( sg, r, c * q);
                    }
                }
            }
        }
    }

    // ---------------- <Z_0>: qubit 0 = index bit 7 = lane bit 4 ----------------
    float acc = 0.0f;
#pragma unroll
    for (int j = 0; j < 8; j++) acc = fmaf(re[j], re[j], fmaf(im[j], im[j], acc));
    if (lane & 16) acc = -acc;
#pragma unroll
    for (int o = 16; o; o >>= 1) acc += __shfl_xor_sync(FULLMASK, acc, o);
    if (lane == 0) out[sample] = acc;
}

extern "C" void kernel_launch(void* const* d_in, const int* in_sizes, int n_in,
                              void* d_out, int out_size) {
    const float* x = (const float*)d_in[0];   // (4096, 8)
    const float* w = (const float*)d_in[1];   // (4, 8, 2)
    float* out = (float*)d_out;               // (4096,)
    const int threads = 256;                  // 8 warps = 8 samples per block
    const int blocks = (BATCHN * 32) / threads;  // 512
    vqc_kernel<<<blocks, threads>>>(x, w, out);
}

// round 5
// speedup vs baseline: 1.3788x; 1.3788x over previous
#include <cuda_runtime.h>
#include <cuda_bf16.h>

#define NQ 8
#define NL 4
#define BATCHN 4096
#define FULLMASK 0xffffffffu

// ---------------- f32x2 packed math helpers (FFMA2/FMUL2 via PTX) ----------------
__device__ __forceinline__ float2 f2fma(float2 a, float2 b, float2 c) {
    float2 d;
    asm("{\n\t"
        ".reg .b64 ra, rb, rc, rd;\n\t"
        "mov.b64 ra, {%2,%3};\n\t"
        "mov.b64 rb, {%4,%5};\n\t"
        "mov.b64 rc, {%6,%7};\n\t"
        "fma.rn.f32x2 rd, ra, rb, rc;\n\t"
        "mov.b64 {%0,%1}, rd;\n\t"
        "}"
        : "=f"(d.x), "=f"(d.y)
        : "f"(a.x), "f"(a.y), "f"(b.x), "f"(b.y), "f"(c.x), "f"(c.y));
    return d;
}
__device__ __forceinline__ float2 f2mul(float2 a, float2 b) {
    float2 d;
    asm("{\n\t"
        ".reg .b64 ra, rb, rd;\n\t"
        "mov.b64 ra, {%2,%3};\n\t"
        "mov.b64 rb, {%4,%5};\n\t"
        "mul.rn.f32x2 rd, ra, rb;\n\t"
        "mov.b64 {%0,%1}, rd;\n\t"
        "}"
        : "=f"(d.x), "=f"(d.y)
        : "f"(a.x), "f"(a.y), "f"(b.x), "f"(b.y));
    return d;
}
__device__ __forceinline__ float2 shflx2(float2 v, int m) {
    v.x = __shfl_xor_sync(FULLMASK, v.x, m);
    v.y = __shfl_xor_sync(FULLMASK, v.y, m);
    return v;
}

// State layout: 8 lanes per sample (sub = lane&7), 32 amplitudes per lane packed
// as float2 PR[16]/PI[16]; amplitude index = sub*32 + 2k + h (h = .x/.y half).
// Qubit q <-> index bit (7-q):
//   q0->sub bit2, q1->sub bit1, q2->sub bit0,
//   q3->k bit3,  q4->k bit2,  q5->k bit1,  q6->k bit0,  q7->packed half.

// RY on a k-bit (qubits 3..6)
__device__ __forceinline__ void ry_reg(float2* PR, float2* PI, float c, float s, int ks) {
    float2 c2 = make_float2(c, c), s2 = make_float2(s, s), n2 = make_float2(-s, -s);
#pragma unroll
    for (int k = 0; k < 16; k++) if (!(k & ks)) {
        const int k2 = k | ks;
        float2 r0 = PR[k], r1 = PR[k2], i0 = PI[k], i1 = PI[k2];
        PR[k]  = f2fma(n2, r1, f2mul(c2, r0));
        PR[k2] = f2fma(s2, r0, f2mul(c2, r1));
        PI[k]  = f2fma(n2, i1, f2mul(c2, i0));
        PI[k2] = f2fma(s2, i0, f2mul(c2, i1));
    }
}
// RY on qubit 7 (packed halves)
__device__ __forceinline__ void ry_pk(float2* PR, float2* PI, float c, float s) {
    float2 c2 = make_float2(c, c), sn = make_float2(-s, s);
#pragma unroll
    for (int k = 0; k < 16; k++) {
        float2 r = PR[k], i = PI[k];
        PR[k] = f2fma(sn, make_float2(r.y, r.x), f2mul(c2, r));
        PI[k] = f2fma(sn, make_float2(i.y, i.x), f2mul(c2, i));
    }
}
// RY on a lane bit (qubits 0..2)
__device__ __forceinline__ void ry_ln(float2* PR, float2* PI, float c, float s, int lb, int sub) {
    const float ss = (sub & lb) ? s : -s;
    float2 c2 = make_float2(c, c), s2 = make_float2(ss, ss);
#pragma unroll
    for (int k = 0; k < 16; k++) {
        float2 pr = shflx2(PR[k], lb);
        float2 pi = shflx2(PI[k], lb);
        PR[k] = f2fma(s2, pr, f2mul(c2, PR[k]));
        PI[k] = f2fma(s2, pi, f2mul(c2, PI[k]));
    }
}
// RZ on qubit 7: sign differs inside the packed pair -> single packed constant
__device__ __forceinline__ void rz_pk(float2* PR, float2* PI, float c, float s) {
    float2 c2 = make_float2(c, c), sg = make_float2(-s, s), ng = make_float2(s, -s);
#pragma unroll
    for (int k = 0; k < 16; k++) {
        float2 r = PR[k], i = PI[k];
        PR[k] = f2fma(ng, i, f2mul(c2, r));
        PI[k] = f2fma(sg, r, f2mul(c2, i));
    }
}
// RZ on a k-bit (qubits 3..6)
__device__ __forceinline__ void rz_reg(float2* PR, float2* PI, float c, float s, int ks) {
    float2 c2 = make_float2(c, c), sp = make_float2(s, s), sm = make_float2(-s, -s);
#pragma unroll
    for (int k = 0; k < 16; k++) {
        float2 sg = (k & ks) ? sp : sm;
        float2 ng = (k & ks) ? sm : sp;
        float2 r = PR[k], i = PI[k];
        PR[k] = f2fma(ng, i, f2mul(c2, r));
        PI[k] = f2fma(sg, r, f2mul(c2, i));
    }
}
// RZ on a lane bit (qubits 0..2)
__device__ __forceinline__ void rz_ln(float2* PR, float2* PI, float c, float s, int lb, int sub) {
    const float g = (sub & lb) ? s : -s;
    float2 c2 = make_float2(c, c), g2 = make_float2(g, g), n2 = make_float2(-g, -g);
#pragma unroll
    for (int k = 0; k < 16; k++) {
        float2 r = PR[k], i = PI[k];
        PR[k] = f2fma(n2, i, f2mul(c2, r));
        PI[k] = f2fma(g2, r, f2mul(c2, i));
    }
}

__global__ __launch_bounds__(64) void vqc_kernel(
    const float* __restrict__ x,      // (4096, 8)
    const float* __restrict__ w,      // (4, 8, 2)
    float* __restrict__ out)          // (4096,)
{
    __shared__ float wc[NL * NQ * 2];
    __shared__ float ws[NL * NQ * 2];
    const int tid = threadIdx.x;
    {   // blockDim == 64 == NL*NQ*2
        float a = 0.5f * w[tid];
        float s, c;
        sincosf(a, &s, &c);
        wc[tid] = c; ws[tid] = s;
    }
    __syncthreads();

    const int lane = tid & 31;
    const int sub  = lane & 7;                 // 3 lane bits of the state index
    const int sample = blockIdx.x * 8 + (tid >> 5) * 4 + ((lane >> 3) & 3);

    // Composed lane permutation for CNOT(q0->q1) then CNOT(q1->q2) (constant!)
    int s1 = (sub & 2) ? (sub ^ 1) : sub;
    const int srclane01 = (lane & 24) | ((s1 & 4) ? (s1 ^ 2) : s1);

    // ---------- Angle encoding as a direct product state (all-real) ----------
    float cq[8], sq[8];
    {
        const float4* xv = (const float4*)(x + sample * NQ);
        float4 xa = __ldg(xv), xb = __ldg(xv + 1);
        float xs[8] = {xa.x, xa.y, xa.z, xa.w, xb.x, xb.y, xb.z, xb.w};
#pragma unroll
        for (int q = 0; q < 8; q++) __sincosf(0.5f * xs[q], &sq[q], &cq[q]);
    }
    float A = ((sub & 4) ? sq[0] : cq[0]) * ((sub & 2) ? sq[1] : cq[1]) *
              ((sub & 1) ? sq[2] : cq[2]);
    float m2[2], m4[4], m8[8], m16[16];
    m2[0] = A * cq[3];  m2[1] = A * sq[3];
#pragma unroll
    for (int b = 0; b < 4; b++)  m4[b]  = m2[b >> 1] * ((b & 1) ? sq[4] : cq[4]);
#pragma unroll
    for (int b = 0; b < 8; b++)  m8[b]  = m4[b >> 1] * ((b & 1) ? sq[5] : cq[5]);
#pragma unroll
    for (int b = 0; b < 16; b++) m16[b] = m8[b >> 1] * ((b & 1) ? sq[6] : cq[6]);

    float2 PR[16], PI[16];
#pragma unroll
    for (int k = 0; k < 16; k++) {
        PR[k] = make_float2(m16[k] * cq[7], m16[k] * sq[7]);
        PI[k] = make_float2(0.0f, 0.0f);
    }

    // ---------------- Variational layers ----------------
#pragma unroll 1
    for (int l = 0; l < NL; l++) {
        // --- CNOT ring (in order i = 0..7) ---
        // i=0 (q0->q1) and i=1 (q1->q2): composed pure lane permutation
#pragma unroll
        for (int k = 0; k < 16; k++) {
            PR[k].x = __shfl_sync(FULLMASK, PR[k].x, srclane01);
            PR[k].y = __shfl_sync(FULLMASK, PR[k].y, srclane01);
            PI[k].x = __shfl_sync(FULLMASK, PI[k].x, srclane01);
            PI[k].y = __shfl_sync(FULLMASK, PI[k].y, srclane01);
        }
        // i=2: c=q2 (sub bit0), t=q3 (k bit3): swap k <-> k+8 where control set
        if (sub & 1) {
#pragma unroll
            for (int k = 0; k < 8; k++) {
                float2 t = PR[k]; PR[k] = PR[k + 8]; PR[k + 8] = t;
                t = PI[k]; PI[k] = PI[k + 8]; PI[k + 8] = t;
            }
        }
        // i=3: c=q3 (k bit3), t=q4 (k bit2): swap (8..11) <-> (12..15)
#pragma unroll
        for (int k = 8; k < 12; k++) {
            float2 t = PR[k]; PR[k] = PR[k + 4]; PR[k + 4] = t;
            t = PI[k]; PI[k] = PI[k + 4]; PI[k + 4] = t;
        }
        // i=4: c=q4 (k bit2), t=q5 (k bit1): swap k<->k+2 for k bit2=1, bit1=0
#pragma unroll
        for (int k = 0; k < 16; k++) if ((k & 4) && !(k & 2)) {
            float2 t = PR[k]; PR[k] = PR[k + 2]; PR[k + 2] = t;
            t = PI[k]; PI[k] = PI[k + 2]; PI[k + 2] = t;
        }
        // i=5: c=q5 (k bit1), t=q6 (k bit0): swap k<->k+1 for k bit1=1, bit0=0
#pragma unroll
        for (int k = 0; k < 16; k++) if ((k & 2) && !(k & 1)) {
            float2 t = PR[k]; PR[k] = PR[k + 1]; PR[k + 1] = t;
            t = PI[k]; PI[k] = PI[k + 1]; PI[k + 1] = t;
        }
        // i=6: c=q6 (k bit0), t=q7 (packed halves): swap halves for odd k
#pragma unroll
        for (int k = 1; k < 16; k += 2) {
            PR[k] = make_float2(PR[k].y, PR[k].x);
            PI[k] = make_float2(PI[k].y, PI[k].x);
        }
        // i=7: c=q7 (odd half .y), t=q0 (lane xor 4): only .y moves
#pragma unroll
        for (int k = 0; k < 16; k++) {
            PR[k].y = __shfl_xor_sync(FULLMASK, PR[k].y, 4);
            PI[k].y = __shfl_xor_sync(FULLMASK, PI[k].y, 4);
        }

        // --- RY then RZ on each qubit ---
        const int lbase = l * 16;
#pragma unroll
        for (int i = 0; i < NQ; i++) {
            const int base = lbase + i * 2;
            const float cy = wc[base],     sy = ws[base];
            const float cz = wc[base + 1], sz = ws[base + 1];
            if (i == 0)      { ry_ln(PR, PI, cy, sy, 4, sub); rz_ln(PR, PI, cz, sz, 4, sub); }
            else if (i == 1) { ry_ln(PR, PI, cy, sy, 2, sub); rz_ln(PR, PI, cz, sz, 2, sub); }
            else if (i == 2) { ry_ln(PR, PI, cy, sy, 1, sub); rz_ln(PR, PI, cz, sz, 1, sub); }
            else if (i == 7) { ry_pk(PR, PI, cy, sy);         rz_pk(PR, PI, cz, sz); }
            else             { ry_reg(PR, PI, cy, sy, 1 << (6 - i));
                               rz_reg(PR, PI, cz, sz, 1 << (6 - i)); }
        }
    }

    // ---------------- <Z_0>: qubit 0 = sub bit2 ----------------
    float acc = 0.0f;
#pragma unroll
    for (int k = 0; k < 16; k++) {
        acc = fmaf(PR[k].x, PR[k].x, acc);
        acc = fmaf(PR[k].y, PR[k].y, acc);
        acc = fmaf(PI[k].x, PI[k].x, acc);
        acc = fmaf(PI[k].y, PI[k].y, acc);
    }
    if (sub & 4) acc = -acc;
    acc += __shfl_xor_sync(FULLMASK, acc, 1);
    acc += __shfl_xor_sync(FULLMASK, acc, 2);
    acc += __shfl_xor_sync(FULLMASK, acc, 4);
    if (sub == 0) out[sample] = acc;
}

extern "C" void kernel_launch(void* const* d_in, const int* in_sizes, int n_in,
                              void* d_out, int out_size) {
    const float* x = (const float*)d_in[0];   // (4096, 8)
    const float* w = (const float*)d_in[1];   // (4, 8, 2)
    float* out = (float*)d_out;               // (4096,)
    // 64 threads = 2 warps = 8 samples per block; 512 blocks total
    vqc_kernel<<<BATCHN / 8, 64>>>(x, w, out);
}

// round 6
// speedup vs baseline: 1.5724x; 1.1404x over previous
#include <cuda_runtime.h>
#include <cuda_bf16.h>

#define NQ 8
#define NL 4
#define BATCHN 4096
#define FULLMASK 0xffffffffu

// ---------------- f32x2 packed math helpers ----------------
__device__ __forceinline__ float2 f2fma(float2 a, float2 b, float2 c) {
    float2 d;
    asm("{\n\t"
        ".reg .b64 ra, rb, rc, rd;\n\t"
        "mov.b64 ra, {%2,%3};\n\t"
        "mov.b64 rb, {%4,%5};\n\t"
        "mov.b64 rc, {%6,%7};\n\t"
        "fma.rn.f32x2 rd, ra, rb, rc;\n\t"
        "mov.b64 {%0,%1}, rd;\n\t"
        "}"
        : "=f"(d.x), "=f"(d.y)
        : "f"(a.x), "f"(a.y), "f"(b.x), "f"(b.y), "f"(c.x), "f"(c.y));
    return d;
}
__device__ __forceinline__ float2 f2mul(float2 a, float2 b) {
    float2 d;
    asm("{\n\t"
        ".reg .b64 ra, rb, rd;\n\t"
        "mov.b64 ra, {%2,%3};\n\t"
        "mov.b64 rb, {%4,%5};\n\t"
        "mul.rn.f32x2 rd, ra, rb;\n\t"
        "mov.b64 {%0,%1}, rd;\n\t"
        "}"
        : "=f"(d.x), "=f"(d.y)
        : "f"(a.x), "f"(a.y), "f"(b.x), "f"(b.y));
    return d;
}
__device__ __forceinline__ float2 shflx2(float2 v, int m) {
    v.x = __shfl_xor_sync(FULLMASK, v.x, m);
    v.y = __shfl_xor_sync(FULLMASK, v.y, m);
    return v;
}

// State layout: 16 lanes per sample (sub = lane&15), 16 amplitudes per lane
// packed as float2 PR[8]/PI[8]; amplitude index = sub*16 + 2k + h.
// Qubit q <-> index bit (7-q):
//   q0->lane b3, q1->lane b2, q2->lane b1, q3->lane b0,
//   q4->k b2,    q5->k b1,    q6->k b0,    q7->packed half h.

__device__ __forceinline__ void ry_reg(float2* PR, float2* PI, float c, float s, int ks) {
    float2 c2 = make_float2(c, c), s2 = make_float2(s, s), n2 = make_float2(-s, -s);
#pragma unroll
    for (int k = 0; k < 8; k++) if (!(k & ks)) {
        const int k2 = k | ks;
        float2 r0 = PR[k], r1 = PR[k2], i0 = PI[k], i1 = PI[k2];
        PR[k]  = f2fma(n2, r1, f2mul(c2, r0));
        PR[k2] = f2fma(s2, r0, f2mul(c2, r1));
        PI[k]  = f2fma(n2, i1, f2mul(c2, i0));
        PI[k2] = f2fma(s2, i0, f2mul(c2, i1));
    }
}
__device__ __forceinline__ void ry_pk(float2* PR, float2* PI, float c, float s) {
    float2 c2 = make_float2(c, c), sn = make_float2(-s, s);
#pragma unroll
    for (int k = 0; k < 8; k++) {
        float2 r = PR[k], i = PI[k];
        PR[k] = f2fma(sn, make_float2(r.y, r.x), f2mul(c2, r));
        PI[k] = f2fma(sn, make_float2(i.y, i.x), f2mul(c2, i));
    }
}
__device__ __forceinline__ void ry_ln(float2* PR, float2* PI, float c, float s, int lb, int sub) {
    const float ss = (sub & lb) ? s : -s;
    float2 c2 = make_float2(c, c), s2 = make_float2(ss, ss);
#pragma unroll
    for (int k = 0; k < 8; k++) {
        float2 pr = shflx2(PR[k], lb);
        float2 pi = shflx2(PI[k], lb);
        PR[k] = f2fma(s2, pr, f2mul(c2, PR[k]));
        PI[k] = f2fma(s2, pi, f2mul(c2, PI[k]));
    }
}
__device__ __forceinline__ void rz_pk(float2* PR, float2* PI, float c, float s) {
    float2 c2 = make_float2(c, c), sg = make_float2(-s, s), ng = make_float2(s, -s);
#pragma unroll
    for (int k = 0; k < 8; k++) {
        float2 r = PR[k], i = PI[k];
        PR[k] = f2fma(ng, i, f2mul(c2, r));
        PI[k] = f2fma(sg, r, f2mul(c2, i));
    }
}
__device__ __forceinline__ void rz_reg(float2* PR, float2* PI, float c, float s, int ks) {
    float2 c2 = make_float2(c, c), sp = make_float2(s, s), sm = make_float2(-s, -s);
#pragma unroll
    for (int k = 0; k < 8; k++) {
        float2 sg = (k & ks) ? sp : sm;
        float2 ng = (k & ks) ? sm : sp;
        float2 r = PR[k], i = PI[k];
        PR[k] = f2fma(ng, i, f2mul(c2, r));
        PI[k] = f2fma(sg, r, f2mul(c2, i));
    }
}
__device__ __forceinline__ void rz_ln(float2* PR, float2* PI, float c, float s, int lb, int sub) {
    const float g = (sub & lb) ? s : -s;
    float2 c2 = make_float2(c, c), g2 = make_float2(g, g), n2 = make_float2(-g, -g);
#pragma unroll
    for (int k = 0; k < 8; k++) {
        float2 r = PR[k], i = PI[k];
        PR[k] = f2fma(n2, i, f2mul(c2, r));
        PI[k] = f2fma(g2, r, f2mul(c2, i));
    }
}

// CNOT ring: control q_i -> target q_{i+1}, i = 0..7 in order.
__device__ __forceinline__ void cnot_ring(float2* PR, float2* PI, int lane, int src012) {
    // i=0,1,2 composed (controls/targets all on lane bits 3..0): index shuffle
#pragma unroll
    for (int k = 0; k < 8; k++) {
        PR[k].x = __shfl_sync(FULLMASK, PR[k].x, src012);
        PR[k].y = __shfl_sync(FULLMASK, PR[k].y, src012);
        PI[k].x = __shfl_sync(FULLMASK, PI[k].x, src012);
        PI[k].y = __shfl_sync(FULLMASK, PI[k].y, src012);
    }
    // i=3: c=q3 (lane b0), t=q4 (k b2): swap k <-> k+4 where control set
    if (lane & 1) {
#pragma unroll
        for (int k = 0; k < 4; k++) {
            float2 t = PR[k]; PR[k] = PR[k + 4]; PR[k + 4] = t;
            t = PI[k]; PI[k] = PI[k + 4]; PI[k + 4] = t;
        }
    }
    // i=4: c=q4 (k b2), t=q5 (k b1): swap (4,6),(5,7)
#pragma unroll
    for (int k = 4; k < 6; k++) {
        float2 t = PR[k]; PR[k] = PR[k + 2]; PR[k + 2] = t;
        t = PI[k]; PI[k] = PI[k + 2]; PI[k + 2] = t;
    }
    // i=5: c=q5 (k b1), t=q6 (k b0): swap (2,3),(6,7)
    {
        float2 t = PR[2]; PR[2] = PR[3]; PR[3] = t;
        t = PI[2]; PI[2] = PI[3]; PI[3] = t;
        t = PR[6]; PR[6] = PR[7]; PR[7] = t;
        t = PI[6]; PI[6] = PI[7]; PI[7] = t;
    }
    // i=6: c=q6 (k b0), t=q7 (half): swap halves for odd k
#pragma unroll
    for (int k = 1; k < 8; k += 2) {
        PR[k] = make_float2(PR[k].y, PR[k].x);
        PI[k] = make_float2(PI[k].y, PI[k].x);
    }
    // i=7: c=q7 (odd half .y), t=q0 (lane b3): only .y moves
#pragma unroll
    for (int k = 0; k < 8; k++) {
        PR[k].y = __shfl_xor_sync(FULLMASK, PR[k].y, 8);
        PI[k].y = __shfl_xor_sync(FULLMASK, PI[k].y, 8);
    }
}

__global__ __launch_bounds__(64) void vqc_kernel(
    const float* __restrict__ x,      // (4096, 8)
    const float* __restrict__ w,      // (4, 8, 2)
    float* __restrict__ out)          // (4096,)
{
    __shared__ float wc[NL * NQ * 2];
    __shared__ float ws[NL * NQ * 2];
    const int tid = threadIdx.x;
    {   // blockDim == 64 == NL*NQ*2
        float a = 0.5f * w[tid];
        float s, c;
        sincosf(a, &s, &c);
        wc[tid] = c; ws[tid] = s;
    }
    __syncthreads();

    const int lane = tid & 31;
    const int sub  = lane & 15;
    const int sample = blockIdx.x * 4 + ((tid >> 5) << 1) + ((lane >> 4) & 1);

    // Composed inverse lane permutation for ring CNOTs i=0,1,2:
    // forward: b2^=b3; b1^=b2'; b0^=b1'. inverse: s3=d3, s2=d2^d3, s1=d1^d2, s0=d0^d1
    const int b3 = (sub >> 3) & 1, b2 = (sub >> 2) & 1, b1 = (sub >> 1) & 1, b0 = sub & 1;
    const int src012 = (lane & 16) | (b3 << 3) | ((b2 ^ b3) << 2) |
                       ((b1 ^ b2) << 1) | (b0 ^ b1);

    // ---------- Angle encoding as direct product state (all-real) ----------
    float cq[8], sq[8];
    {
        const float4* xv = (const float4*)(x + sample * NQ);
        float4 xa = __ldg(xv), xb = __ldg(xv + 1);
        float xs[8] = {xa.x, xa.y, xa.z, xa.w, xb.x, xb.y, xb.z, xb.w};
#pragma unroll
        for (int q = 0; q < 8; q++) __sincosf(0.5f * xs[q], &sq[q], &cq[q]);
    }
    // lane factor: q0..q3 from lane bits 3..0
    float A = (b3 ? sq[0] : cq[0]) * (b2 ? sq[1] : cq[1]) *
              (b1 ? sq[2] : cq[2]) * (b0 ? sq[3] : cq[3]);
    float u2[2], u4[4], u8[8];
    u2[0] = A * cq[4];  u2[1] = A * sq[4];                       // k bit2 = q4
#pragma unroll
    for (int b = 0; b < 4; b++) u4[b] = u2[b >> 1] * ((b & 1) ? sq[5] : cq[5]);
#pragma unroll
    for (int k = 0; k < 8; k++) u8[k] = u4[k >> 1] * ((k & 1) ? sq[6] : cq[6]);

    float2 PR[8], PI[8];
#pragma unroll
    for (int k = 0; k < 8; k++) {
        PR[k] = make_float2(u8[k] * cq[7], u8[k] * sq[7]);       // half = q7
        PI[k] = make_float2(0.0f, 0.0f);
    }

    // ---------------- Layers 0..2: full ring + all rotations ----------------
#pragma unroll 1
    for (int l = 0; l < NL - 1; l++) {
        cnot_ring(PR, PI, lane, src012);
        const int lbase = l * 16;
#pragma unroll
        for (int i = 0; i < NQ; i++) {
            const int base = lbase + i * 2;
            const float cy = wc[base],     sy = ws[base];
            const float cz = wc[base + 1], sz = ws[base + 1];
            if (i < 4) {
                const int lb = 8 >> i;
                ry_ln(PR, PI, cy, sy, lb, sub);
                rz_ln(PR, PI, cz, sz, lb, sub);
            } else if (i == 7) {
                ry_pk(PR, PI, cy, sy);
                rz_pk(PR, PI, cz, sz);
            } else {
                const int ks = 1 << (6 - i);
                ry_reg(PR, PI, cy, sy, ks);
                rz_reg(PR, PI, cz, sz, ks);
            }
        }
    }

    // ---------------- Layer 3: ring + RY(q0) only ----------------
    // All other final-layer rotations act on qubits != q0 (preserve the q0
    // marginal) or are diagonal (preserve |amp|^2) -> no effect on <Z_0>.
    cnot_ring(PR, PI, lane, src012);
    {
        const int base = 3 * 16;  // (l=3, i=0, RY)
        ry_ln(PR, PI, wc[base], ws[base], 8, sub);
    }

    // ---------------- <Z_0>: q0 = lane bit3 ----------------
    float2 a2 = make_float2(0.0f, 0.0f);
#pragma unroll
    for (int k = 0; k < 8; k++) {
        a2 = f2fma(PR[k], PR[k], a2);
        a2 = f2fma(PI[k], PI[k], a2);
    }
    float acc = a2.x + a2.y;
    if (sub & 8) acc = -acc;
    acc += __shfl_xor_sync(FULLMASK, acc, 1);
    acc += __shfl_xor_sync(FULLMASK, acc, 2);
    acc += __shfl_xor_sync(FULLMASK, acc, 4);
    acc += __shfl_xor_sync(FULLMASK, acc, 8);
    if (sub == 0) out[sample] = acc;
}

extern "C" void kernel_launch(void* const* d_in, const int* in_sizes, int n_in,
                              void* d_out, int out_size) {
    const float* x = (const float*)d_in[0];   // (4096, 8)
    const float* w = (const float*)d_in[1];   // (4, 8, 2)
    float* out = (float*)d_out;               // (4096,)
    // 64 threads = 2 warps = 4 samples per block; 1024 blocks, 2048 warps total
    vqc_kernel<<<BATCHN / 4, 64>>>(x, w, out);
}